// round 12
// baseline (speedup 1.0000x reference)
#include <cuda_runtime.h>
#include <cuda_bf16.h>
#include <math.h>

#define BZ 32
#define SZ 128
#define HZ 768
#define MH_ 6
#define KK 4

__constant__ float c_inv[8] = {1.f, 1.f/2.f, 1.f/3.f, 1.f/4.f, 1.f/5.f, 1.f/6.f, 1.f/7.f, 1.f/8.f};

__device__ unsigned long long g_cand[BZ * 2 * 4 * 4];  // [b][type][quarter][4]
__device__ unsigned int g_tick[BZ];                    // zero-init; elected resets

#define CE(x, y) { unsigned long long _a = (x), _b = (y); (x) = _a > _b ? _a : _b; (y) = _a > _b ? _b : _a; }

#define WARP_MERGE4(k0, k1, k2, k3)                                            \
    _Pragma("unroll")                                                          \
    for (int off = 16; off; off >>= 1) {                                       \
        unsigned long long o0 = __shfl_xor_sync(0xFFFFFFFFu, k0, off);         \
        unsigned long long o1 = __shfl_xor_sync(0xFFFFFFFFu, k1, off);         \
        unsigned long long o2 = __shfl_xor_sync(0xFFFFFFFFu, k2, off);         \
        unsigned long long o3 = __shfl_xor_sync(0xFFFFFFFFu, k3, off);         \
        unsigned long long c0 = k0 > o3 ? k0 : o3;                             \
        unsigned long long c1 = k1 > o2 ? k1 : o2;                             \
        unsigned long long c2 = k2 > o1 ? k2 : o1;                             \
        unsigned long long c3 = k3 > o0 ? k3 : o0;                             \
        CE(c0, c2); CE(c1, c3); CE(c0, c1); CE(c2, c3);                        \
        k0 = c0; k1 = c1; k2 = c2; k3 = c3;                                    \
    }

// out layout (floats): implicit[0,512) explicit[512,2560) hs[2560,35328) ts[35328,68096)

__global__ __launch_bounds__(512, 1) void k_all(
    const float* __restrict__ emb,
    const int* __restrict__ mask,
    const float* __restrict__ wh,
    const float* __restrict__ bh_,
    const float* __restrict__ wt,
    const float* __restrict__ bt_,
    const float* __restrict__ wi,
    const float* __restrict__ bi,
    const float* __restrict__ we,
    const float* __restrict__ be,
    float* __restrict__ out)
{
    __shared__ __align__(16) float swh[HZ];
    __shared__ __align__(16) float swt[HZ];
    __shared__ float sdot[2][40];
    __shared__ unsigned long long cand[2][32];
    __shared__ float topv[2][KK];
    __shared__ int   topi[2][KK];
    __shared__ float partial[16][8];
    __shared__ float sbias[8];
    __shared__ float s_bh, s_bt;
    __shared__ int s_flag, s_len;

    const int b = blockIdx.x, q = blockIdx.y;
    const int tid = threadIdx.x;
    const int warp = tid >> 5, lane = tid & 31;
    const float* eb = emb + b * (SZ * HZ);

    // ---- stage wh/wt to smem; scalars; mask length ----
    {
        float4* swh4 = (float4*)swh;
        float4* swt4 = (float4*)swt;
        if (tid < 384) {
            if (tid < 192) swh4[tid] = ((const float4*)wh)[tid];
            else           swt4[tid - 192] = ((const float4*)wt)[tid - 192];
        }
        if (tid == 0) s_flag = 0;
        if (tid < 4)            sbias[tid] = bi[tid];
        else if (tid < 8)       sbias[tid] = be[tid - 4];
        if (tid == 8)  s_bh = bh_[0];
        if (tid == 9)  s_bt = bt_[0];
        if (warp == 13) {
            int4 mv = ((const int4*)(mask + b * SZ))[lane];
            int v = mv.x + mv.y + mv.z + mv.w;
#pragma unroll
            for (int off = 16; off; off >>= 1) v += __shfl_xor_sync(0xFFFFFFFFu, v, off);
            if (lane == 0) s_len = v;
        }
    }
    __syncthreads();

    // ---- phase A: row dots, 16 warps x 3 rows, split accumulators ----
    {
        const int lr0 = warp * 3;
        float ah[3], at[3];
        const float4* swh4 = (const float4*)swh;
        const float4* swt4 = (const float4*)swt;
#pragma unroll
        for (int r = 0; r < 3; r++) {
            int lr = lr0 + r;
            int gr = q * 32 + lr;
            float ahA = 0.f, ahB = 0.f, atA = 0.f, atB = 0.f;
            if (lr < 40 && gr < SZ) {
                const float4* rp = (const float4*)(eb + gr * HZ);
                float4 v[6];
#pragma unroll
                for (int i = 0; i < 6; i++) v[i] = rp[lane + 32 * i];
#pragma unroll
                for (int i = 0; i < 3; i++) {
                    float4 wv = swh4[lane + 32 * i];
                    float4 tv = swt4[lane + 32 * i];
                    ahA += v[i].x * wv.x + v[i].y * wv.y + v[i].z * wv.z + v[i].w * wv.w;
                    atA += v[i].x * tv.x + v[i].y * tv.y + v[i].z * tv.z + v[i].w * tv.w;
                }
#pragma unroll
                for (int i = 3; i < 6; i++) {
                    float4 wv = swh4[lane + 32 * i];
                    float4 tv = swt4[lane + 32 * i];
                    ahB += v[i].x * wv.x + v[i].y * wv.y + v[i].z * wv.z + v[i].w * wv.w;
                    atB += v[i].x * tv.x + v[i].y * tv.y + v[i].z * tv.z + v[i].w * tv.w;
                }
            }
            ah[r] = ahA + ahB;
            at[r] = atA + atB;
        }
#pragma unroll
        for (int off = 16; off; off >>= 1) {
#pragma unroll
            for (int r = 0; r < 3; r++) {
                ah[r] += __shfl_xor_sync(0xFFFFFFFFu, ah[r], off);
                at[r] += __shfl_xor_sync(0xFFFFFFFFu, at[r], off);
            }
        }
        if (lane == 0) {
#pragma unroll
            for (int r = 0; r < 3; r++) {
                int lr = lr0 + r;
                if (lr < 40) {
                    sdot[0][lr] = at[r];
                    sdot[1][lr] = ah[r];
                }
            }
        }
    }
    __syncthreads();

    // ---- scores: warp = type*8 + width; bitonic warp top-4 ----
    {
        const int type = warp >> 3;
        const int m = warp & 7;
        const int sg = q * 32 + lane;
        const int gidx = m * SZ + sg;
        float s = 0.f;
        for (int r = 0; r <= m; r++) s += sdot[type][lane + r];
        const int len = s_len;
        bool valid = ((sg + m) < len) && (type == 0 || m < MH_);
        float bias = type ? s_bh : s_bt;
        float v = valid ? 1.f / (1.f + __expf(-(s * c_inv[m] + bias))) : -1.f;
        out[(type ? 2560 : 35328) + b * 1024 + gidx] = v;

        unsigned u = __float_as_uint(v);
        u = (u & 0x80000000u) ? ~u : (u | 0x80000000u);
        unsigned long long k0 = ((unsigned long long)u << 32) | (unsigned)(0xFFFFFFFFu - gidx);
        unsigned long long k1 = 0ull, k2 = 0ull, k3 = 0ull;
        WARP_MERGE4(k0, k1, k2, k3);
        if (lane == 0) {
            cand[type][m * 4 + 0] = k0; cand[type][m * 4 + 1] = k1;
            cand[type][m * 4 + 2] = k2; cand[type][m * 4 + 3] = k3;
        }
    }
    __syncthreads();

    // ---- block merge 32 -> 4 -> g_cand ----
    if (warp < 2) {
        unsigned long long k0 = cand[warp][lane], k1 = 0ull, k2 = 0ull, k3 = 0ull;
        WARP_MERGE4(k0, k1, k2, k3);
        if (lane == 0) {
            unsigned long long* dst = &g_cand[((b * 2 + warp) * 4 + q) * 4];
            dst[0] = k0; dst[1] = k1; dst[2] = k2; dst[3] = k3;
        }
    }

    // ---- election ----
    __threadfence();
    __syncthreads();
    if (tid == 0) {
        unsigned old = atomicAdd(&g_tick[b], 1u);
        if (old == 3u) s_flag = 1;
    }
    __syncthreads();
    if (!s_flag) return;
    if (tid == 0) g_tick[b] = 0;
    __threadfence();

    // ================= Tail =================
    if (warp < 2) {
        unsigned long long k0 = (lane < 16) ? g_cand[(b * 2 + warp) * 16 + lane] : 0ull;
        unsigned long long k1 = 0ull, k2 = 0ull, k3 = 0ull;
        WARP_MERGE4(k0, k1, k2, k3);
        if (lane == 0) {
            unsigned long long ks[4] = {k0, k1, k2, k3};
#pragma unroll
            for (int k = 0; k < KK; k++) {
                unsigned hi = (unsigned)(ks[k] >> 32);
                unsigned lo = (unsigned)ks[k];
                float v = (hi & 0x80000000u) ? __uint_as_float(hi ^ 0x80000000u)
                                             : __uint_as_float(~hi);
                topv[warp][k] = v;
                topi[warp][k] = (int)(0xFFFFFFFFu - lo);
            }
        }
    }
    __syncthreads();

    // rep dots: 2 warps per span; ALL loads batched upfront, split accumulators
    {
        const int type = warp >> 3;
        const int span = (warp >> 1) & 3;
        const int half = warp & 1;
        const int idx = topi[type][span];
        const bool valid = topv[type][span] > 0.f;
        const int m = idx >> 7, s = idx & 127;
        const float invw = c_inv[m];
        const float4* wi4 = (const float4*)wi;
        const float4* we4 = (const float4*)we;
        const int c0 = lane + 96 * half;

        float acc[8] = {0.f,0.f,0.f,0.f,0.f,0.f,0.f,0.f};
        if (valid) {
            // batch-load all 24 row float4s (rows beyond m predicated to zero)
            float4 rv[8][3];
#pragma unroll
            for (int r = 0; r < 8; r++) {
                if (r <= m) {
                    const float4* rp = (const float4*)(eb + (s + r) * HZ);
#pragma unroll
                    for (int i = 0; i < 3; i++) rv[r][i] = rp[c0 + 32 * i];
                } else {
#pragma unroll
                    for (int i = 0; i < 3; i++) rv[r][i] = make_float4(0.f,0.f,0.f,0.f);
                }
            }
            // tree-sum rows (depth 3, not 8)
            float4 sum[3];
#pragma unroll
            for (int i = 0; i < 3; i++) {
                float4 s01, s23, s45, s67, sA, sB;
                s01.x = rv[0][i].x + rv[1][i].x; s01.y = rv[0][i].y + rv[1][i].y;
                s01.z = rv[0][i].z + rv[1][i].z; s01.w = rv[0][i].w + rv[1][i].w;
                s23.x = rv[2][i].x + rv[3][i].x; s23.y = rv[2][i].y + rv[3][i].y;
                s23.z = rv[2][i].z + rv[3][i].z; s23.w = rv[2][i].w + rv[3][i].w;
                s45.x = rv[4][i].x + rv[5][i].x; s45.y = rv[4][i].y + rv[5][i].y;
                s45.z = rv[4][i].z + rv[5][i].z; s45.w = rv[4][i].w + rv[5][i].w;
                s67.x = rv[6][i].x + rv[7][i].x; s67.y = rv[6][i].y + rv[7][i].y;
                s67.z = rv[6][i].z + rv[7][i].z; s67.w = rv[6][i].w + rv[7][i].w;
                sA.x = s01.x + s23.x; sA.y = s01.y + s23.y;
                sA.z = s01.z + s23.z; sA.w = s01.w + s23.w;
                sB.x = s45.x + s67.x; sB.y = s45.y + s67.y;
                sB.z = s45.z + s67.z; sB.w = s45.w + s67.w;
                sum[i].x = (sA.x + sB.x) * invw; sum[i].y = (sA.y + sB.y) * invw;
                sum[i].z = (sA.z + sB.z) * invw; sum[i].w = (sA.w + sB.w) * invw;
            }
            // batch-load all weight float4s, then FMA with split accumulators
            if (type == 0) {
                float4 wvv[3][4], evv[3][4];
#pragma unroll
                for (int i = 0; i < 3; i++) {
                    int h4 = c0 + 32 * i;
#pragma unroll
                    for (int j = 0; j < 4; j++) {
                        wvv[i][j] = wi4[4 * h4 + j];
                        evv[i][j] = we4[HZ + 4 * h4 + j];
                    }
                }
                float a0[8] = {0,0,0,0,0,0,0,0}, a1[8] = {0,0,0,0,0,0,0,0};
#pragma unroll
                for (int i = 0; i < 3; i++) {
                    const float sv[4] = {sum[i].x, sum[i].y, sum[i].z, sum[i].w};
#pragma unroll
                    for (int j = 0; j < 4; j++) {
                        float* t = (j & 1) ? a1 : a0;
                        t[0] += sv[j] * wvv[i][j].x; t[1] += sv[j] * wvv[i][j].y;
                        t[2] += sv[j] * wvv[i][j].z; t[3] += sv[j] * wvv[i][j].w;
                        t[4] += sv[j] * evv[i][j].x; t[5] += sv[j] * evv[i][j].y;
                        t[6] += sv[j] * evv[i][j].z; t[7] += sv[j] * evv[i][j].w;
                    }
                }
#pragma unroll
                for (int j = 0; j < 8; j++) acc[j] = a0[j] + a1[j];
            } else {
                float4 evv[3][4];
#pragma unroll
                for (int i = 0; i < 3; i++) {
                    int h4 = c0 + 32 * i;
#pragma unroll
                    for (int j = 0; j < 4; j++) evv[i][j] = we4[4 * h4 + j];
                }
                float a0[4] = {0,0,0,0}, a1[4] = {0,0,0,0};
#pragma unroll
                for (int i = 0; i < 3; i++) {
                    const float sv[4] = {sum[i].x, sum[i].y, sum[i].z, sum[i].w};
#pragma unroll
                    for (int j = 0; j < 4; j++) {
                        float* t = (j & 1) ? a1 : a0;
                        t[0] += sv[j] * evv[i][j].x; t[1] += sv[j] * evv[i][j].y;
                        t[2] += sv[j] * evv[i][j].z; t[3] += sv[j] * evv[i][j].w;
                    }
                }
#pragma unroll
                for (int j = 0; j < 4; j++) acc[j] = a0[j] + a1[j];
            }
        }
        const int nred = (type == 0) ? 8 : 4;
        for (int j = 0; j < nred; j++)
#pragma unroll
            for (int off = 16; off; off >>= 1)
                acc[j] += __shfl_xor_sync(0xFFFFFFFFu, acc[j], off);
        if (lane == 0) {
#pragma unroll
            for (int j = 0; j < 8; j++) partial[warp][j] = acc[j];
        }
    }
    __syncthreads();

    // logits
    if (tid < 64) {
        int k = tid >> 4, i = (tid >> 2) & 3, j = tid & 3;
        bool pv = (topv[1][k] > 0.f) && (topv[0][i] > 0.f);
        float val = sbias[4 + j];
        if (pv) val += partial[8 + 2*k][j] + partial[8 + 2*k + 1][j]
                     + partial[2*i][4 + j] + partial[2*i + 1][4 + j];
        out[512 + b * 64 + tid] = val;
    } else if (tid < 80) {
        int t2 = tid - 64;
        int i = t2 >> 2, j = t2 & 3;
        float val = sbias[j];
        if (topv[0][i] > 0.f) val += partial[2*i][j] + partial[2*i + 1][j];
        out[b * 16 + t2] = val;
    }
}

extern "C" void kernel_launch(void* const* d_in, const int* in_sizes, int n_in,
                              void* d_out, int out_size)
{
    const float* emb = (const float*)d_in[0];
    const int*   msk = (const int*)d_in[1];
    const float* wh  = (const float*)d_in[2];
    const float* bh  = (const float*)d_in[3];
    const float* wt  = (const float*)d_in[4];
    const float* bt  = (const float*)d_in[5];
    const float* wi  = (const float*)d_in[6];
    const float* bi  = (const float*)d_in[7];
    const float* we  = (const float*)d_in[8];
    const float* be  = (const float*)d_in[9];
    float* out = (float*)d_out;

    dim3 g(BZ, 4, 1);
    k_all<<<g, 512>>>(emb, msk, wh, bh, wt, bt, wi, bi, we, be, out);
}

// round 13
// speedup vs baseline: 1.1429x; 1.1429x over previous
#include <cuda_runtime.h>
#include <cuda_bf16.h>
#include <math.h>

#define BZ 32
#define SZ 128
#define HZ 768
#define MH_ 6
#define KK 4

__constant__ float c_inv[8] = {1.f, 1.f/2.f, 1.f/3.f, 1.f/4.f, 1.f/5.f, 1.f/6.f, 1.f/7.f, 1.f/8.f};

__device__ unsigned long long g_cand[BZ * 2 * 4 * 4];  // [b][type][quarter][4]
__device__ unsigned int g_tick[BZ];                    // zero-init; tail resets

#define CE(x, y) { unsigned long long _a = (x), _b = (y); (x) = _a > _b ? _a : _b; (y) = _a > _b ? _b : _a; }

#define WARP_MERGE4(k0, k1, k2, k3)                                            \
    _Pragma("unroll")                                                          \
    for (int off = 16; off; off >>= 1) {                                       \
        unsigned long long o0 = __shfl_xor_sync(0xFFFFFFFFu, k0, off);         \
        unsigned long long o1 = __shfl_xor_sync(0xFFFFFFFFu, k1, off);         \
        unsigned long long o2 = __shfl_xor_sync(0xFFFFFFFFu, k2, off);         \
        unsigned long long o3 = __shfl_xor_sync(0xFFFFFFFFu, k3, off);         \
        unsigned long long c0 = k0 > o3 ? k0 : o3;                             \
        unsigned long long c1 = k1 > o2 ? k1 : o2;                             \
        unsigned long long c2 = k2 > o1 ? k2 : o1;                             \
        unsigned long long c3 = k3 > o0 ? k3 : o0;                             \
        CE(c0, c2); CE(c1, c3); CE(c0, c1); CE(c2, c3);                        \
        k0 = c0; k1 = c1; k2 = c2; k3 = c3;                                    \
    }

// out layout (floats): implicit[0,512) explicit[512,2560) hs[2560,35328) ts[35328,68096)

__global__ __launch_bounds__(512, 1) void k_all(
    const float* __restrict__ emb,
    const int* __restrict__ mask,
    const float* __restrict__ wh,
    const float* __restrict__ bh_,
    const float* __restrict__ wt,
    const float* __restrict__ bt_,
    const float* __restrict__ wi,
    const float* __restrict__ bi,
    const float* __restrict__ we,
    const float* __restrict__ be,
    float* __restrict__ out)
{
    __shared__ __align__(16) float swh[HZ];           // phase: wh     (3 KB)
    __shared__ __align__(16) float swt[HZ];           // phase: wt     (3 KB)
    __shared__ __align__(16) float swi[HZ * 4];       // tail: wi      (12 KB)
    __shared__ __align__(16) float swe[2 * HZ * 4];   // tail: we      (24 KB)
    __shared__ float sdot[2][40];
    __shared__ unsigned long long cand[2][32];
    __shared__ float topv[2][KK];
    __shared__ int   topi[2][KK];
    __shared__ float partial[16][8];
    __shared__ float sbias[8];
    __shared__ float s_bh, s_bt;
    __shared__ int s_len;

    const int bid = blockIdx.x;
    const int tid = threadIdx.x;
    const int warp = tid >> 5, lane = tid & 31;

    if (bid < 128) {
        // ================= PHASE BLOCK (b, q) — R9 verbatim, minus tail ====
        const int b = bid >> 2, q = bid & 3;
        const float* eb = emb + b * (SZ * HZ);

        {
            float4* swh4 = (float4*)swh;
            float4* swt4 = (float4*)swt;
            if (tid < 384) {
                if (tid < 192) swh4[tid] = ((const float4*)wh)[tid];
                else           swt4[tid - 192] = ((const float4*)wt)[tid - 192];
            }
            if (tid == 8)  s_bh = bh_[0];
            if (tid == 9)  s_bt = bt_[0];
            if (warp == 13) {
                int4 mv = ((const int4*)(mask + b * SZ))[lane];
                int v = mv.x + mv.y + mv.z + mv.w;
#pragma unroll
                for (int off = 16; off; off >>= 1) v += __shfl_xor_sync(0xFFFFFFFFu, v, off);
                if (lane == 0) s_len = v;
            }
        }
        __syncthreads();

        // phase A: row dots for local rows 0..39 (16 warps x 3 rows)
        {
            const int lr0 = warp * 3;
            float ah[3] = {0.f,0.f,0.f}, at[3] = {0.f,0.f,0.f};
            const float4* swh4 = (const float4*)swh;
            const float4* swt4 = (const float4*)swt;
#pragma unroll
            for (int r = 0; r < 3; r++) {
                int lr = lr0 + r;
                int gr = q * 32 + lr;
                if (lr < 40 && gr < SZ) {
                    const float4* rp = (const float4*)(eb + gr * HZ);
                    float4 v[6];
#pragma unroll
                    for (int i = 0; i < 6; i++) v[i] = rp[lane + 32 * i];
#pragma unroll
                    for (int i = 0; i < 6; i++) {
                        float4 wv = swh4[lane + 32 * i];
                        float4 tv = swt4[lane + 32 * i];
                        ah[r] += v[i].x * wv.x + v[i].y * wv.y
                               + v[i].z * wv.z + v[i].w * wv.w;
                        at[r] += v[i].x * tv.x + v[i].y * tv.y
                               + v[i].z * tv.z + v[i].w * tv.w;
                    }
                }
            }
#pragma unroll
            for (int off = 16; off; off >>= 1) {
#pragma unroll
                for (int r = 0; r < 3; r++) {
                    ah[r] += __shfl_xor_sync(0xFFFFFFFFu, ah[r], off);
                    at[r] += __shfl_xor_sync(0xFFFFFFFFu, at[r], off);
                }
            }
            if (lane == 0) {
#pragma unroll
                for (int r = 0; r < 3; r++) {
                    int lr = lr0 + r;
                    if (lr < 40) {
                        sdot[0][lr] = at[r];
                        sdot[1][lr] = ah[r];
                    }
                }
            }
        }
        __syncthreads();

        // scores: warp = type*8 + width; bitonic warp top-4
        {
            const int type = warp >> 3;
            const int m = warp & 7;
            const int sg = q * 32 + lane;
            const int gidx = m * SZ + sg;
            float s = 0.f;
            for (int r = 0; r <= m; r++) s += sdot[type][lane + r];
            const int len = s_len;
            bool valid = ((sg + m) < len) && (type == 0 || m < MH_);
            float bias = type ? s_bh : s_bt;
            float v = valid ? 1.f / (1.f + __expf(-(s * c_inv[m] + bias))) : -1.f;
            out[(type ? 2560 : 35328) + b * 1024 + gidx] = v;

            unsigned u = __float_as_uint(v);
            u = (u & 0x80000000u) ? ~u : (u | 0x80000000u);
            unsigned long long k0 = ((unsigned long long)u << 32) | (unsigned)(0xFFFFFFFFu - gidx);
            unsigned long long k1 = 0ull, k2 = 0ull, k3 = 0ull;
            WARP_MERGE4(k0, k1, k2, k3);
            if (lane == 0) {
                cand[type][m * 4 + 0] = k0; cand[type][m * 4 + 1] = k1;
                cand[type][m * 4 + 2] = k2; cand[type][m * 4 + 3] = k3;
            }
        }
        __syncthreads();

        // block merge 32 -> 4 -> g_cand
        if (warp < 2) {
            unsigned long long k0 = cand[warp][lane], k1 = 0ull, k2 = 0ull, k3 = 0ull;
            WARP_MERGE4(k0, k1, k2, k3);
            if (lane == 0) {
                unsigned long long* dst = &g_cand[((b * 2 + warp) * 4 + q) * 4];
                dst[0] = k0; dst[1] = k1; dst[2] = k2; dst[3] = k3;
            }
        }

        // signal completion
        __threadfence();
        __syncthreads();
        if (tid == 0) atomicAdd(&g_tick[b], 1u);
        return;
    }

    // ================= TAIL BLOCK (one per batch) ==========================
    {
        const int b = bid - 128;
        const float* eb = emb + b * (SZ * HZ);

        // prefetch weights + biases into smem (overlaps the spin below)
        {
            float4* swi4 = (float4*)swi;
            float4* swe4 = (float4*)swe;
            const float4* wi4g = (const float4*)wi;
            const float4* we4g = (const float4*)we;
#pragma unroll
            for (int i = 0; i < 2; i++) {
                int j = tid + 512 * i;
                if (j < 768) swi4[j] = wi4g[j];
            }
#pragma unroll
            for (int i = 0; i < 3; i++) {
                int j = tid + 512 * i;
                if (j < 1536) swe4[j] = we4g[j];
            }
            if (tid < 4)       sbias[tid] = bi[tid];
            else if (tid < 8)  sbias[tid] = be[tid - 4];
        }

        // spin until all 4 phase blocks of this batch have arrived
        if (tid == 0) {
            while (*(volatile unsigned*)&g_tick[b] < 4u) __nanosleep(64);
            g_tick[b] = 0;   // reset for next graph replay
        }
        __syncthreads();
        __threadfence();     // acquire: order g_cand reads after the flag

        // merge 16 candidates per type (warp0 targets, warp1 holders)
        if (warp < 2) {
            unsigned long long k0 = (lane < 16) ? g_cand[(b * 2 + warp) * 16 + lane] : 0ull;
            unsigned long long k1 = 0ull, k2 = 0ull, k3 = 0ull;
            WARP_MERGE4(k0, k1, k2, k3);
            if (lane == 0) {
                unsigned long long ks[4] = {k0, k1, k2, k3};
#pragma unroll
                for (int k = 0; k < KK; k++) {
                    unsigned hi = (unsigned)(ks[k] >> 32);
                    unsigned lo = (unsigned)ks[k];
                    float v = (hi & 0x80000000u) ? __uint_as_float(hi ^ 0x80000000u)
                                                 : __uint_as_float(~hi);
                    topv[warp][k] = v;
                    topi[warp][k] = (int)(0xFFFFFFFFu - lo);
                }
            }
        }
        __syncthreads();

        // rep dots: 2 warps per span (warps 0-7 target, 8-15 holder), weights in smem
        {
            const int type = warp >> 3;
            const int span = (warp >> 1) & 3;
            const int half = warp & 1;
            const int idx = topi[type][span];
            const bool valid = topv[type][span] > 0.f;
            const int m = idx >> 7, s = idx & 127;
            const float invw = c_inv[m];
            const float4* swi4 = (const float4*)swi;
            const float4* swe4 = (const float4*)swe;

            float acc[8] = {0.f,0.f,0.f,0.f,0.f,0.f,0.f,0.f};
            if (valid) {
                float4 sum[3];
#pragma unroll
                for (int i = 0; i < 3; i++) sum[i] = make_float4(0.f,0.f,0.f,0.f);
                const int c0 = lane + 96 * half;
#pragma unroll
                for (int r = 0; r < 8; r++) {
                    if (r <= m) {
                        const float4* rp = (const float4*)(eb + (s + r) * HZ);
#pragma unroll
                        for (int i = 0; i < 3; i++) {
                            float4 a = rp[c0 + 32 * i];
                            sum[i].x += a.x; sum[i].y += a.y;
                            sum[i].z += a.z; sum[i].w += a.w;
                        }
                    }
                }
#pragma unroll
                for (int i = 0; i < 3; i++) {
                    int h4 = c0 + 32 * i;
                    float sv[4] = {sum[i].x * invw, sum[i].y * invw,
                                   sum[i].z * invw, sum[i].w * invw};
#pragma unroll
                    for (int j = 0; j < 4; j++) {
                        int f = 4 * h4 + j;
                        if (type == 0) {
                            float4 wv = swi4[f];
                            acc[0] += sv[j] * wv.x; acc[1] += sv[j] * wv.y;
                            acc[2] += sv[j] * wv.z; acc[3] += sv[j] * wv.w;
                            float4 ev = swe4[HZ + f];
                            acc[4] += sv[j] * ev.x; acc[5] += sv[j] * ev.y;
                            acc[6] += sv[j] * ev.z; acc[7] += sv[j] * ev.w;
                        } else {
                            float4 ev = swe4[f];
                            acc[0] += sv[j] * ev.x; acc[1] += sv[j] * ev.y;
                            acc[2] += sv[j] * ev.z; acc[3] += sv[j] * ev.w;
                        }
                    }
                }
            }
#pragma unroll
            for (int off = 16; off; off >>= 1)
#pragma unroll
                for (int j = 0; j < 8; j++)
                    acc[j] += __shfl_xor_sync(0xFFFFFFFFu, acc[j], off);
            if (lane == 0) {
#pragma unroll
                for (int j = 0; j < 8; j++) partial[warp][j] = acc[j];
            }
        }
        __syncthreads();

        // logits
        if (tid < 64) {
            int k = tid >> 4, i = (tid >> 2) & 3, j = tid & 3;
            bool pv = (topv[1][k] > 0.f) && (topv[0][i] > 0.f);
            float val = sbias[4 + j];
            if (pv) val += partial[8 + 2*k][j] + partial[8 + 2*k + 1][j]
                         + partial[2*i][4 + j] + partial[2*i + 1][4 + j];
            out[512 + b * 64 + tid] = val;
        } else if (tid < 80) {
            int t2 = tid - 64;
            int i = t2 >> 2, j = t2 & 3;
            float val = sbias[j];
            if (topv[0][i] > 0.f) val += partial[2*i][j] + partial[2*i + 1][j];
            out[b * 16 + t2] = val;
        }
    }
}

extern "C" void kernel_launch(void* const* d_in, const int* in_sizes, int n_in,
                              void* d_out, int out_size)
{
    const float* emb = (const float*)d_in[0];
    const int*   msk = (const int*)d_in[1];
    const float* wh  = (const float*)d_in[2];
    const float* bh  = (const float*)d_in[3];
    const float* wt  = (const float*)d_in[4];
    const float* bt  = (const float*)d_in[5];
    const float* wi  = (const float*)d_in[6];
    const float* bi  = (const float*)d_in[7];
    const float* we  = (const float*)d_in[8];
    const float* be  = (const float*)d_in[9];
    float* out = (float*)d_out;

    k_all<<<160, 512>>>(emb, msk, wh, bh, wt, bt, wi, bi, we, be, out);
}